// round 5
// baseline (speedup 1.0000x reference)
#include <cuda_runtime.h>
#include <cstdint>

// TreeModel: depth-14 perfect binary heap, 32767 nodes, 16384 leaves, dim 512.
// out[0..16383] = dot(x[i], sum of deltas along root->leaf path)
// out[16384]    = sq[0] + sum_{n>=1} sq[n]/max(heights[n]-heights[parent],1e-7)
//
// Pass A: per level-8 subtree (256 CTAs x 128): expand path sums to level 11,
//         write 2048 cum rows (4MB scratch). Fold sq terms for levels 0..11.
// Pass B: per level-11 subtree (2048 CTAs x 256): ALL data via cp.async.bulk
//         (cum row + contiguous level-12/13 blocks + leaf deltas + x), two
//         mbarrier groups for overlap; compute from SMEM only. sq levels 12..14
//         fused; last-CTA (fence+counter) reduces all partials in fixed order.
// No data atomics -> bitwise deterministic.

#define DIM 512
#define N_LEAVES 16384
#define NCTA_B 2048

__device__ float g_cum[2048 * DIM];          // level-11 cumulative rows (4MB)
__device__ float g_sqA[256];                 // pass-A sq partials
__device__ float g_part[NCTA_B];             // pass-B sq partials
__device__ unsigned int g_count = 0;

__device__ __forceinline__ float warp_sum(float v) {
#pragma unroll
    for (int o = 16; o > 0; o >>= 1) v += __shfl_down_sync(0xffffffffu, v, o);
    return v;
}

__device__ __forceinline__ float inv_branch(const float* __restrict__ heights, int n) {
    return 1.0f / fmaxf(heights[n] - heights[(n - 1) >> 1], 1e-7f);
}

__device__ __forceinline__ float sq4(float4 v) {
    return fmaf(v.x, v.x, fmaf(v.y, v.y, fmaf(v.z, v.z, v.w * v.w)));
}

__device__ __forceinline__ float4 add4(float4 a, float4 b) {
    return make_float4(a.x + b.x, a.y + b.y, a.z + b.z, a.w + b.w);
}

// ---------------- Pass A: expand cum weights to level 11 --------------------
__global__ __launch_bounds__(128) void expand_kernel(const float* __restrict__ deltas,
                                                     const float* __restrict__ heights) {
    __shared__ float red[4];
    const int bid = blockIdx.x;              // level-8 subtree id (0..255)
    const int col = threadIdx.x;             // float4 column
    const int w   = threadIdx.x >> 5;
    const int lane = threadIdx.x & 31;

    float sqacc = 0.f;

    const int n8 = 255 + bid;
    int anc[9];
    anc[8] = n8;
#pragma unroll
    for (int l = 8; l > 0; --l) anc[l - 1] = (anc[l] - 1) >> 1;

    float4 c8 = make_float4(0.f, 0.f, 0.f, 0.f);
#pragma unroll
    for (int l = 0; l <= 8; ++l) {
        const float4* row = (const float4*)(deltas + (size_t)anc[l] * DIM);
        float4 v = row[col];
        c8 = add4(c8, v);
        if ((bid & ((1 << (8 - l)) - 1)) == 0) {          // owner CTA
            float inv = (l == 0) ? 1.0f : inv_branch(heights, anc[l]);
            sqacc = fmaf(sq4(v), inv, sqacc);
        }
    }

    float4 c9[2];
#pragma unroll
    for (int j = 0; j < 2; ++j) {
        const int n = 511 + 2 * bid + j;
        float4 v = ((const float4*)(deltas + (size_t)n * DIM))[col];
        sqacc = fmaf(sq4(v), inv_branch(heights, n), sqacc);
        c9[j] = add4(c8, v);
    }
    float4 c10[4];
#pragma unroll
    for (int j = 0; j < 4; ++j) {
        const int n = 1023 + 4 * bid + j;
        float4 v = ((const float4*)(deltas + (size_t)n * DIM))[col];
        sqacc = fmaf(sq4(v), inv_branch(heights, n), sqacc);
        c10[j] = add4(c9[j >> 1], v);
    }
#pragma unroll
    for (int j = 0; j < 8; ++j) {
        const int n = 2047 + 8 * bid + j;
        float4 v = ((const float4*)(deltas + (size_t)n * DIM))[col];
        sqacc = fmaf(sq4(v), inv_branch(heights, n), sqacc);
        float4 c = add4(c10[j >> 1], v);
        ((float4*)(g_cum + (size_t)(8 * bid + j) * DIM))[col] = c;
    }

    sqacc = warp_sum(sqacc);
    if (lane == 0) red[w] = sqacc;
    __syncthreads();
    if (threadIdx.x == 0) g_sqA[bid] = red[0] + red[1] + red[2] + red[3];
}

// ---------------- Pass B: all-TMA streaming kernel --------------------------
__global__ __launch_bounds__(256) void tree_kernel(const float* __restrict__ x,
                                                   const float* __restrict__ deltas,
                                                   const float* __restrict__ heights,
                                                   float* __restrict__ out) {
    __shared__ float4 cumS[128];      //  2 KB  level-11 cum row
    __shared__ float4 d12S[2][128];   //  4 KB  level-12 rows
    __shared__ float4 d13S[4][128];   //  8 KB  level-13 rows
    __shared__ float4 dl[8][128];     // 16 KB  leaf delta rows
    __shared__ float4 xs[8][128];     // 16 KB  x rows
    __shared__ float  redL[32];
    __shared__ float  redS[8];
    __shared__ int    is_last;
    __shared__ __align__(8) unsigned long long mbar0, mbar1;

    const int bid  = blockIdx.x;      // level-11 subtree id
    const int tid  = threadIdx.x;
    const int col  = tid & 127;
    const int g    = tid >> 7;        // slice 0/1
    const int w    = tid >> 5;
    const int lane = tid & 31;

    const unsigned mb0 = (unsigned)__cvta_generic_to_shared(&mbar0);
    const unsigned mb1 = (unsigned)__cvta_generic_to_shared(&mbar1);

    if (tid == 0) {
        asm volatile("mbarrier.init.shared.b64 [%0], %1;" :: "r"(mb0), "r"(1));
        asm volatile("mbarrier.init.shared.b64 [%0], %1;" :: "r"(mb1), "r"(1));
        asm volatile("fence.proxy.async.shared::cta;" ::: "memory");
        asm volatile("mbarrier.arrive.expect_tx.shared.b64 _, [%0], %1;"
                     :: "r"(mb0), "r"(14336u));
        asm volatile("mbarrier.arrive.expect_tx.shared.b64 _, [%0], %1;"
                     :: "r"(mb1), "r"(32768u));
        const unsigned a_cum = (unsigned)__cvta_generic_to_shared(cumS);
        const unsigned a_d12 = (unsigned)__cvta_generic_to_shared(d12S);
        const unsigned a_d13 = (unsigned)__cvta_generic_to_shared(d13S);
        const unsigned a_dl  = (unsigned)__cvta_generic_to_shared(dl);
        const unsigned a_xs  = (unsigned)__cvta_generic_to_shared(xs);
        const float* s_cum = g_cum + (size_t)bid * DIM;
        const float* s_d12 = deltas + (size_t)(4095 + 2 * bid) * DIM;
        const float* s_d13 = deltas + (size_t)(8191 + 4 * bid) * DIM;
        const float* s_dl  = deltas + (size_t)(N_LEAVES - 1 + 8 * bid) * DIM;
        const float* s_xs  = x + (size_t)(8 * bid) * DIM;
        asm volatile("cp.async.bulk.shared::cta.global.mbarrier::complete_tx::bytes [%0], [%1], %2, [%3];"
                     :: "r"(a_cum), "l"(s_cum), "r"(2048u),  "r"(mb0) : "memory");
        asm volatile("cp.async.bulk.shared::cta.global.mbarrier::complete_tx::bytes [%0], [%1], %2, [%3];"
                     :: "r"(a_d12), "l"(s_d12), "r"(4096u),  "r"(mb0) : "memory");
        asm volatile("cp.async.bulk.shared::cta.global.mbarrier::complete_tx::bytes [%0], [%1], %2, [%3];"
                     :: "r"(a_d13), "l"(s_d13), "r"(8192u),  "r"(mb0) : "memory");
        asm volatile("cp.async.bulk.shared::cta.global.mbarrier::complete_tx::bytes [%0], [%1], %2, [%3];"
                     :: "r"(a_dl),  "l"(s_dl),  "r"(16384u), "r"(mb1) : "memory");
        asm volatile("cp.async.bulk.shared::cta.global.mbarrier::complete_tx::bytes [%0], [%1], %2, [%3];"
                     :: "r"(a_xs),  "l"(s_xs),  "r"(16384u), "r"(mb1) : "memory");
    }
    __syncthreads();                  // orders mbarrier.init for all threads

    float sqacc = 0.f;

    // heights-derived scalars (tiny broadcast loads, overlap with TMA)
    const int n12 = 4095 + 2 * bid + g;
    const float inv12 = inv_branch(heights, n12);
    float inv13[2], inv14[4];
#pragma unroll
    for (int j = 0; j < 2; ++j) inv13[j] = inv_branch(heights, 8191 + 4 * bid + 2 * g + j);
#pragma unroll
    for (int j = 0; j < 4; ++j) inv14[j] = inv_branch(heights, N_LEAVES - 1 + 8 * bid + 4 * g + j);

    // ---- wait group 0: weight path -----------------------------------------
    asm volatile(
        "{\n\t.reg .pred p;\n\t"
        "W0_%=:\n\t"
        "mbarrier.try_wait.parity.acquire.cta.shared::cta.b64 p, [%0], 0;\n\t"
        "@!p bra W0_%=;\n\t}" :: "r"(mb0) : "memory");

    float4 c12;
    {
        float4 v = d12S[g][col];
        sqacc = fmaf(sq4(v), inv12, sqacc);
        c12 = add4(cumS[col], v);
    }
    float4 c13[2];
#pragma unroll
    for (int j = 0; j < 2; ++j) {
        float4 v = d13S[2 * g + j][col];
        sqacc = fmaf(sq4(v), inv13[j], sqacc);
        c13[j] = add4(c12, v);
    }

    // ---- wait group 1: streaming leaves ------------------------------------
    asm volatile(
        "{\n\t.reg .pred p;\n\t"
        "W1_%=:\n\t"
        "mbarrier.try_wait.parity.acquire.cta.shared::cta.b64 p, [%0], 0;\n\t"
        "@!p bra W1_%=;\n\t}" :: "r"(mb1) : "memory");

    float acc[4];
#pragma unroll
    for (int j = 0; j < 4; ++j) {
        const int li = 4 * g + j;
        float4 dv = dl[li][col];
        float4 xv = xs[li][col];
        sqacc = fmaf(sq4(dv), inv14[j], sqacc);
        float4 wv = c13[j >> 1];
        float t;
        t = xv.x * (wv.x + dv.x);
        t = fmaf(xv.y, wv.y + dv.y, t);
        t = fmaf(xv.z, wv.z + dv.z, t);
        t = fmaf(xv.w, wv.w + dv.w, t);
        acc[j] = t;
    }

    // ---- reductions ---------------------------------------------------------
#pragma unroll
    for (int j = 0; j < 4; ++j) acc[j] = warp_sum(acc[j]);
    if (lane == 0) {
        const int ws = w & 3;
#pragma unroll
        for (int j = 0; j < 4; ++j) redL[(g * 4 + j) * 4 + ws] = acc[j];
    }
    sqacc = warp_sum(sqacc);
    if (lane == 0) redS[w] = sqacc;
    __syncthreads();

    if (tid < 8) {
        float r = redL[tid * 4] + redL[tid * 4 + 1] + redL[tid * 4 + 2] + redL[tid * 4 + 3];
        out[bid * 8 + tid] = r;
    }
    if (tid == 0) {
        float t = 0.f;
#pragma unroll
        for (int j = 0; j < 8; ++j) t += redS[j];
        g_part[bid] = t;
        __threadfence();
        unsigned prev = atomicAdd(&g_count, 1u);
        is_last = (prev == NCTA_B - 1) ? 1 : 0;
    }
    __syncthreads();

    // ---- last CTA: deterministic final reduction ---------------------------
    if (is_last) {
        const volatile float* gp = g_part;
        const volatile float* ga = g_sqA;
        float sm = ga[tid & 255] * ((tid < 256) ? 1.f : 0.f);
#pragma unroll
        for (int r = 0; r < 8; ++r) sm += gp[tid + 256 * r];
        sm = warp_sum(sm);
        if (lane == 0) redS[w] = sm;
        __syncthreads();
        if (tid == 0) {
            float t = 0.f;
#pragma unroll
            for (int j = 0; j < 8; ++j) t += redS[j];
            out[N_LEAVES] = t;
            g_count = 0;              // reset for next graph replay
        }
    }
}

extern "C" void kernel_launch(void* const* d_in, const int* in_sizes, int n_in,
                              void* d_out, int out_size) {
    const float* x       = (const float*)d_in[0];
    const float* deltas  = (const float*)d_in[1];
    const float* heights = (const float*)d_in[2];
    float* out = (float*)d_out;

    expand_kernel<<<256, 128>>>(deltas, heights);
    tree_kernel<<<NCTA_B, 256>>>(x, deltas, heights, out);
}

// round 6
// speedup vs baseline: 1.0548x; 1.0548x over previous
#include <cuda_runtime.h>
#include <cstdint>

// TreeModel: depth-14 perfect binary heap, 32767 nodes, 16384 leaves, dim 512.
// out[0..16383] = dot(x[i], sum of deltas along root->leaf path)
// out[16384]    = sq[0] + sum_{n>=1} sq[n]/max(heights[n]-heights[parent],1e-7)
//
// Single kernel, 1024 CTAs (one per level-10 subtree) x 512 threads, ALL data
// via cp.async.bulk (zero LDG on the data path):
//   mb0: 11 upper ancestor rows (scattered, 2KB each) + lvl11 pair + lvl12
//        quad + lvl13 oct (contiguous) = 50KB weight region.
//   mb1: leaf chunk0 (8 delta rows + 8 x rows, 32KB).
//   mb2: leaf chunk1 (32KB) -- issued AFTER the weight region is consumed into
//        registers, reusing its SMEM (dyn smem total 84KB -> 2 CTAs/SM,
//        168KB in flight per SM).
// sq/branch terms folded in with owner-CTA (levels 0..10) and slice-owner
// (11..14) tricks. fence+counter last-CTA final reduce. Deterministic.

#define DIM 512
#define N_LEAVES 16384
#define NCTA 1024

// float4-unit offsets into dynamic smem
#define UP_OFF   0        // 11 rows x 128
#define D11_OFF  1408     // 2 rows
#define D12_OFF  1664     // 4 rows
#define D13_OFF  2176     // 8 rows
#define DL0_OFF  3200     // 8 rows
#define XS0_OFF  4224     // 8 rows
#define DL1_OFF  0        // reuse of UP region
#define XS1_OFF  1024     // reuse of UP/D11/D12 region (dead by then)
#define DYN_SMEM (5248 * 16)

__device__ float g_part[NCTA];
__device__ unsigned int g_count = 0;

__device__ __forceinline__ float warp_sum(float v) {
#pragma unroll
    for (int o = 16; o > 0; o >>= 1) v += __shfl_down_sync(0xffffffffu, v, o);
    return v;
}
__device__ __forceinline__ float inv_branch(const float* __restrict__ h, int n) {
    return 1.0f / fmaxf(h[n] - h[(n - 1) >> 1], 1e-7f);
}
__device__ __forceinline__ float sq4(float4 v) {
    return fmaf(v.x, v.x, fmaf(v.y, v.y, fmaf(v.z, v.z, v.w * v.w)));
}
__device__ __forceinline__ float4 add4(float4 a, float4 b) {
    return make_float4(a.x + b.x, a.y + b.y, a.z + b.z, a.w + b.w);
}

__device__ __forceinline__ void bulk_cp(unsigned dst, const float* src, unsigned bytes, unsigned mb) {
    asm volatile("cp.async.bulk.shared::cta.global.mbarrier::complete_tx::bytes [%0], [%1], %2, [%3];"
                 :: "r"(dst), "l"(src), "r"(bytes), "r"(mb) : "memory");
}
__device__ __forceinline__ void mb_wait(unsigned mb) {
    asm volatile(
        "{\n\t.reg .pred p;\n\t"
        "W_%=:\n\t"
        "mbarrier.try_wait.parity.acquire.cta.shared::cta.b64 p, [%0], 0;\n\t"
        "@!p bra W_%=;\n\t}" :: "r"(mb) : "memory");
}

__global__ __launch_bounds__(512, 2) void tree_kernel(const float* __restrict__ x,
                                                      const float* __restrict__ deltas,
                                                      const float* __restrict__ heights,
                                                      float* __restrict__ out) {
    extern __shared__ float4 sm[];
    __shared__ float redL[64];        // 16 leaves x 4 warps-in-slice
    __shared__ float redS[16];
    __shared__ int   is_last;
    __shared__ __align__(8) unsigned long long mbar[3];

    const int b    = blockIdx.x;      // level-10 subtree id
    const int tid  = threadIdx.x;
    const int col  = tid & 127;       // float4 column
    const int g    = tid >> 7;        // slice 0..3
    const int w    = tid >> 5;        // warp 0..15
    const int ws   = w & 3;           // warp within slice
    const int lane = tid & 31;

    int anc[11];
    anc[10] = 1023 + b;
#pragma unroll
    for (int l = 10; l > 0; --l) anc[l - 1] = (anc[l] - 1) >> 1;

    const unsigned mb0 = (unsigned)__cvta_generic_to_shared(&mbar[0]);
    const unsigned mb1 = (unsigned)__cvta_generic_to_shared(&mbar[1]);
    const unsigned mb2 = (unsigned)__cvta_generic_to_shared(&mbar[2]);
    const unsigned smb = (unsigned)__cvta_generic_to_shared(sm);

    if (tid == 0) {
        asm volatile("mbarrier.init.shared.b64 [%0], %1;" :: "r"(mb0), "r"(1));
        asm volatile("mbarrier.init.shared.b64 [%0], %1;" :: "r"(mb1), "r"(1));
        asm volatile("mbarrier.init.shared.b64 [%0], %1;" :: "r"(mb2), "r"(1));
        asm volatile("fence.proxy.async.shared::cta;" ::: "memory");
        asm volatile("mbarrier.arrive.expect_tx.shared.b64 _, [%0], %1;" :: "r"(mb0), "r"(51200u));
        asm volatile("mbarrier.arrive.expect_tx.shared.b64 _, [%0], %1;" :: "r"(mb1), "r"(32768u));
#pragma unroll
        for (int l = 0; l <= 10; ++l)
            bulk_cp(smb + (UP_OFF + l * 128) * 16, deltas + (size_t)anc[l] * DIM, 2048u, mb0);
        bulk_cp(smb + D11_OFF * 16, deltas + (size_t)(2047 + 2 * b) * DIM,  4096u, mb0);
        bulk_cp(smb + D12_OFF * 16, deltas + (size_t)(4095 + 4 * b) * DIM,  8192u, mb0);
        bulk_cp(smb + D13_OFF * 16, deltas + (size_t)(8191 + 8 * b) * DIM, 16384u, mb0);
        bulk_cp(smb + DL0_OFF * 16, deltas + (size_t)(N_LEAVES - 1 + 16 * b) * DIM, 16384u, mb1);
        bulk_cp(smb + XS0_OFF * 16, x + (size_t)(16 * b) * DIM, 16384u, mb1);
    }
    __syncthreads();                  // mbarrier init visible to all

    // scalar inv factors (tiny broadcast loads; overlap with TMA)
    float inv14v[4], inv13v[2];
#pragma unroll
    for (int c = 0; c < 2; ++c) {
#pragma unroll
        for (int j = 0; j < 2; ++j)
            inv14v[c * 2 + j] = inv_branch(heights, N_LEAVES - 1 + 16 * b + 8 * c + 4 * j + g);
        inv13v[c] = inv_branch(heights, 8191 + 8 * b + 4 * c + 2 * (g & 1) + (g >> 1));
    }
    const float inv12 = inv_branch(heights, 4095 + 4 * b + g);
    const float inv11 = (g < 2) ? inv_branch(heights, 2047 + 2 * b + g) : 0.f;

    float sqacc = 0.f;

    // ---------------- weight phase (mb0) ------------------------------------
    mb_wait(mb0);

    float4 cum = make_float4(0.f, 0.f, 0.f, 0.f);
#pragma unroll
    for (int l = 0; l <= 10; ++l) {
        float4 v = sm[UP_OFF + l * 128 + col];
        cum = add4(cum, v);
        if ((l & 3) == g && (b & ((1 << (10 - l)) - 1)) == 0) {     // owner CTA+slice
            float inv = (l == 0) ? 1.0f : inv_branch(heights, anc[l]);
            sqacc = fmaf(sq4(v), inv, sqacc);
        }
    }
    float4 d11a = sm[D11_OFF + col];
    float4 d11b = sm[D11_OFF + 128 + col];
    if (g < 2) {
        float4 dv = (g == 0) ? d11a : d11b;
        sqacc = fmaf(sq4(dv), inv11, sqacc);
    }
    float4 c11_0 = add4(cum, d11a);
    float4 c11_1 = add4(cum, d11b);
    float4 c12v[4];
#pragma unroll
    for (int p = 0; p < 4; ++p) {
        float4 v = sm[D12_OFF + p * 128 + col];
        if (p == g) sqacc = fmaf(sq4(v), inv12, sqacc);
        c12v[p] = add4((p < 2) ? c11_0 : c11_1, v);
    }
    __syncthreads();                  // weight region fully consumed

    if (tid == 0) {                   // issue chunk1 into reclaimed space
        asm volatile("mbarrier.arrive.expect_tx.shared.b64 _, [%0], %1;" :: "r"(mb2), "r"(32768u));
        bulk_cp(smb + DL1_OFF * 16, deltas + (size_t)(N_LEAVES - 1 + 16 * b + 8) * DIM, 16384u, mb2);
        bulk_cp(smb + XS1_OFF * 16, x + (size_t)(16 * b + 8) * DIM, 16384u, mb2);
    }

    // ---------------- leaf chunk 0 (mb1) ------------------------------------
    mb_wait(mb1);
#pragma unroll
    for (int j = 0; j < 2; ++j) {
        const int li = 4 * j + g;                 // leaf 0..7
        float4 d13v = sm[D13_OFF + (li >> 1) * 128 + col];
        float4 dv   = sm[DL0_OFF + li * 128 + col];
        float4 xv   = sm[XS0_OFF + li * 128 + col];
        if (j == (g & 1)) sqacc = fmaf(sq4(d13v), inv13v[0], sqacc);
        sqacc = fmaf(sq4(dv), inv14v[j], sqacc);
        float4 wv = add4(add4(c12v[j], d13v), dv);
        float t;
        t = xv.x * wv.x;
        t = fmaf(xv.y, wv.y, t);
        t = fmaf(xv.z, wv.z, t);
        t = fmaf(xv.w, wv.w, t);
        t = warp_sum(t);
        if (lane == 0) redL[li * 4 + ws] = t;
    }

    // ---------------- leaf chunk 1 (mb2) ------------------------------------
    mb_wait(mb2);
#pragma unroll
    for (int j = 0; j < 2; ++j) {
        const int li = 8 + 4 * j + g;             // leaf 8..15
        const int r  = 4 * j + g;
        float4 d13v = sm[D13_OFF + (li >> 1) * 128 + col];
        float4 dv   = sm[DL1_OFF + r * 128 + col];
        float4 xv   = sm[XS1_OFF + r * 128 + col];
        if (j == (g & 1)) sqacc = fmaf(sq4(d13v), inv13v[1], sqacc);
        sqacc = fmaf(sq4(dv), inv14v[2 + j], sqacc);
        float4 wv = add4(add4(c12v[2 + j], d13v), dv);
        float t;
        t = xv.x * wv.x;
        t = fmaf(xv.y, wv.y, t);
        t = fmaf(xv.z, wv.z, t);
        t = fmaf(xv.w, wv.w, t);
        t = warp_sum(t);
        if (lane == 0) redL[li * 4 + ws] = t;
    }

    // ---------------- reductions --------------------------------------------
    sqacc = warp_sum(sqacc);
    if (lane == 0) redS[w] = sqacc;
    __syncthreads();

    if (tid < 16) {
        float r = redL[tid * 4] + redL[tid * 4 + 1] + redL[tid * 4 + 2] + redL[tid * 4 + 3];
        out[16 * b + tid] = r;
    }
    if (tid == 0) {
        float t = 0.f;
#pragma unroll
        for (int j = 0; j < 16; ++j) t += redS[j];
        g_part[b] = t;
        __threadfence();
        unsigned prev = atomicAdd(&g_count, 1u);
        is_last = (prev == NCTA - 1) ? 1 : 0;
    }
    __syncthreads();

    // ---------------- last CTA: deterministic final reduce -------------------
    if (is_last) {
        const volatile float* gp = g_part;
        float s = gp[tid] + gp[tid + 512];
        s = warp_sum(s);
        if (lane == 0) redS[w] = s;
        __syncthreads();
        if (tid == 0) {
            float t = 0.f;
#pragma unroll
            for (int j = 0; j < 16; ++j) t += redS[j];
            out[N_LEAVES] = t;
            g_count = 0;              // reset for next graph replay
        }
    }
}

extern "C" void kernel_launch(void* const* d_in, const int* in_sizes, int n_in,
                              void* d_out, int out_size) {
    const float* x       = (const float*)d_in[0];
    const float* deltas  = (const float*)d_in[1];
    const float* heights = (const float*)d_in[2];
    float* out = (float*)d_out;

    cudaFuncSetAttribute(tree_kernel, cudaFuncAttributeMaxDynamicSharedMemorySize, DYN_SMEM);
    tree_kernel<<<NCTA, 512, DYN_SMEM>>>(x, deltas, heights, out);
}

// round 7
// speedup vs baseline: 1.2138x; 1.1507x over previous
#include <cuda_runtime.h>
#include <cstdint>

// TreeModel: depth-14 perfect binary heap, 32767 nodes, 16384 leaves, dim 512.
// out[0..16383] = dot(x[i], sum of deltas along root->leaf path)
// out[16384]    = sq[0] + sum_{n>=1} sq[n]/max(heights[n]-heights[parent],1e-7)
//
// 2048 CTAs (one per level-11 subtree) x 256 threads, 54KB smem, 4 CTAs/SM:
//  - mb0 (TMA, issued t=0): ancestor rows at levels 9,10,11 + lvl-12 pair +
//    lvl-13 quad (18KB) -- the per-CTA-unique, DRAM-latency data.
//  - mb1 (TMA, issued t=0): 8 leaf delta rows + 8 x rows (32KB).
//  - LDG (overlapped with TMA flight): levels 0..8 only -- L2-hot rows shared
//    by >=8 CTAs -- slice-split 2-way + 4KB SMEM exchange.
//  - sq/branch terms folded in with owner-CTA + slice-parity gating.
//  - fence+counter last-CTA reduces 2048 partials in fixed order.
// No data atomics -> bitwise deterministic.

#define DIM 512
#define N_LEAVES 16384
#define NCTA 2048

// float4-unit offsets into dynamic smem (128 float4 per row)
#define U9_OFF   0
#define U10_OFF  128
#define U11_OFF  256
#define D12_OFF  384      // 2 rows
#define D13_OFF  640      // 4 rows
#define DL_OFF   1152     // 8 rows
#define XS_OFF   2176     // 8 rows
#define SP_OFF   3200     // 2 rows (exchange)
#define DYN_SMEM (3456 * 16)

__device__ float g_part[NCTA];
__device__ unsigned int g_count = 0;

__device__ __forceinline__ float warp_sum(float v) {
#pragma unroll
    for (int o = 16; o > 0; o >>= 1) v += __shfl_down_sync(0xffffffffu, v, o);
    return v;
}
__device__ __forceinline__ float inv_branch(const float* __restrict__ h, int n) {
    return 1.0f / fmaxf(h[n] - h[(n - 1) >> 1], 1e-7f);
}
__device__ __forceinline__ float sq4(float4 v) {
    return fmaf(v.x, v.x, fmaf(v.y, v.y, fmaf(v.z, v.z, v.w * v.w)));
}
__device__ __forceinline__ float4 add4(float4 a, float4 b) {
    return make_float4(a.x + b.x, a.y + b.y, a.z + b.z, a.w + b.w);
}
__device__ __forceinline__ void bulk_cp(unsigned dst, const float* src, unsigned bytes, unsigned mb) {
    asm volatile("cp.async.bulk.shared::cta.global.mbarrier::complete_tx::bytes [%0], [%1], %2, [%3];"
                 :: "r"(dst), "l"(src), "r"(bytes), "r"(mb) : "memory");
}
__device__ __forceinline__ void mb_wait(unsigned mb) {
    asm volatile(
        "{\n\t.reg .pred p;\n\t"
        "W_%=:\n\t"
        "mbarrier.try_wait.parity.acquire.cta.shared::cta.b64 p, [%0], 0;\n\t"
        "@!p bra W_%=;\n\t}" :: "r"(mb) : "memory");
}

__global__ __launch_bounds__(256) void tree_kernel(const float* __restrict__ x,
                                                   const float* __restrict__ deltas,
                                                   const float* __restrict__ heights,
                                                   float* __restrict__ out) {
    extern __shared__ float4 sm[];
    __shared__ float redL[32];        // 8 leaves x 4 warps-in-slice
    __shared__ float redS[8];
    __shared__ int   is_last;
    __shared__ __align__(8) unsigned long long mbar[2];

    const int b    = blockIdx.x;      // level-11 subtree id
    const int tid  = threadIdx.x;
    const int col  = tid & 127;       // float4 column
    const int g    = tid >> 7;        // slice 0/1
    const int w    = tid >> 5;        // warp 0..7
    const int ws   = w & 3;
    const int lane = tid & 31;

    int anc[12];
    anc[11] = 2047 + b;
#pragma unroll
    for (int l = 11; l > 0; --l) anc[l - 1] = (anc[l] - 1) >> 1;

    const unsigned mb0 = (unsigned)__cvta_generic_to_shared(&mbar[0]);
    const unsigned mb1 = (unsigned)__cvta_generic_to_shared(&mbar[1]);
    const unsigned smb = (unsigned)__cvta_generic_to_shared(sm);

    if (tid == 0) {
        asm volatile("mbarrier.init.shared.b64 [%0], %1;" :: "r"(mb0), "r"(1));
        asm volatile("mbarrier.init.shared.b64 [%0], %1;" :: "r"(mb1), "r"(1));
        asm volatile("fence.proxy.async.shared::cta;" ::: "memory");
        asm volatile("mbarrier.arrive.expect_tx.shared.b64 _, [%0], %1;" :: "r"(mb0), "r"(18432u));
        asm volatile("mbarrier.arrive.expect_tx.shared.b64 _, [%0], %1;" :: "r"(mb1), "r"(32768u));
        bulk_cp(smb + U9_OFF  * 16, deltas + (size_t)anc[9]  * DIM, 2048u,  mb0);
        bulk_cp(smb + U10_OFF * 16, deltas + (size_t)anc[10] * DIM, 2048u,  mb0);
        bulk_cp(smb + U11_OFF * 16, deltas + (size_t)anc[11] * DIM, 2048u,  mb0);
        bulk_cp(smb + D12_OFF * 16, deltas + (size_t)(4095 + 2 * b) * DIM, 4096u,  mb0);
        bulk_cp(smb + D13_OFF * 16, deltas + (size_t)(8191 + 4 * b) * DIM, 8192u,  mb0);
        bulk_cp(smb + DL_OFF  * 16, deltas + (size_t)(N_LEAVES - 1 + 8 * b) * DIM, 16384u, mb1);
        bulk_cp(smb + XS_OFF  * 16, x + (size_t)(8 * b) * DIM, 16384u, mb1);
    }
    __syncthreads();                  // mbarrier init visible to all

    float sqacc = 0.f;

    // ---------------- levels 0..8: slice-split LDG (L2-hot), overlaps TMA ---
    {
        float4 s = make_float4(0.f, 0.f, 0.f, 0.f);
#pragma unroll
        for (int l = 0; l <= 8; ++l) {
            if ((l & 1) == g) {
                float4 v = ((const float4*)(deltas + (size_t)anc[l] * DIM))[col];
                s = add4(s, v);
                if ((b & ((1 << (11 - l)) - 1)) == 0) {         // owner CTA
                    float inv = (l == 0) ? 1.0f : inv_branch(heights, anc[l]);
                    sqacc = fmaf(sq4(v), inv, sqacc);
                }
            }
        }
        sm[SP_OFF + g * 128 + col] = s;
    }

    // scalar inv factors (broadcast loads, overlap with TMA)
    const int n12 = 4095 + 2 * b + g;
    const float inv12 = inv_branch(heights, n12);
    float inv13[2], inv14[4];
#pragma unroll
    for (int j = 0; j < 2; ++j) inv13[j] = inv_branch(heights, 8191 + 4 * b + 2 * g + j);
#pragma unroll
    for (int j = 0; j < 4; ++j) inv14[j] = inv_branch(heights, N_LEAVES - 1 + 8 * b + 4 * g + j);

    __syncthreads();
    float4 cum = add4(sm[SP_OFF + col], sm[SP_OFF + 128 + col]);

    // ---------------- levels 9..13 from TMA (mb0) ----------------------------
    mb_wait(mb0);
    {
        float4 v9  = sm[U9_OFF  + col];
        float4 v10 = sm[U10_OFF + col];
        float4 v11 = sm[U11_OFF + col];
        if (g == 1 && (b & 3) == 0) sqacc = fmaf(sq4(v9),  inv_branch(heights, anc[9]),  sqacc);
        if (g == 0 && (b & 1) == 0) sqacc = fmaf(sq4(v10), inv_branch(heights, anc[10]), sqacc);
        if (g == 1)                 sqacc = fmaf(sq4(v11), inv_branch(heights, anc[11]), sqacc);
        cum = add4(add4(cum, v9), add4(v10, v11));
    }
    float4 c12;
    {
        float4 v = sm[D12_OFF + g * 128 + col];
        sqacc = fmaf(sq4(v), inv12, sqacc);
        c12 = add4(cum, v);
    }
    float4 c13[2];
#pragma unroll
    for (int j = 0; j < 2; ++j) {
        float4 v = sm[D13_OFF + (2 * g + j) * 128 + col];
        sqacc = fmaf(sq4(v), inv13[j], sqacc);
        c13[j] = add4(c12, v);
    }

    // ---------------- leaves from TMA (mb1) ----------------------------------
    mb_wait(mb1);
    float acc[4];
#pragma unroll
    for (int j = 0; j < 4; ++j) {
        const int li = 4 * g + j;
        float4 dv = sm[DL_OFF + li * 128 + col];
        float4 xv = sm[XS_OFF + li * 128 + col];
        sqacc = fmaf(sq4(dv), inv14[j], sqacc);
        float4 wv = add4(c13[j >> 1], dv);
        float t;
        t = xv.x * wv.x;
        t = fmaf(xv.y, wv.y, t);
        t = fmaf(xv.z, wv.z, t);
        t = fmaf(xv.w, wv.w, t);
        acc[j] = t;
    }

    // ---------------- reductions ---------------------------------------------
#pragma unroll
    for (int j = 0; j < 4; ++j) acc[j] = warp_sum(acc[j]);
    if (lane == 0) {
#pragma unroll
        for (int j = 0; j < 4; ++j) redL[(g * 4 + j) * 4 + ws] = acc[j];
    }
    sqacc = warp_sum(sqacc);
    if (lane == 0) redS[w] = sqacc;
    __syncthreads();

    if (tid < 8) {
        float r = redL[tid * 4] + redL[tid * 4 + 1] + redL[tid * 4 + 2] + redL[tid * 4 + 3];
        out[8 * b + tid] = r;
    }
    if (tid == 0) {
        float t = 0.f;
#pragma unroll
        for (int j = 0; j < 8; ++j) t += redS[j];
        g_part[b] = t;
        __threadfence();
        unsigned prev = atomicAdd(&g_count, 1u);
        is_last = (prev == NCTA - 1) ? 1 : 0;
    }
    __syncthreads();

    // ---------------- last CTA: deterministic final reduce -------------------
    if (is_last) {
        const volatile float* gp = g_part;
        float s = 0.f;
#pragma unroll
        for (int r = 0; r < 8; ++r) s += gp[tid + 256 * r];
        s = warp_sum(s);
        if (lane == 0) redS[w] = s;
        __syncthreads();
        if (tid == 0) {
            float t = 0.f;
#pragma unroll
            for (int j = 0; j < 8; ++j) t += redS[j];
            out[N_LEAVES] = t;
            g_count = 0;              // reset for next graph replay
        }
    }
}

extern "C" void kernel_launch(void* const* d_in, const int* in_sizes, int n_in,
                              void* d_out, int out_size) {
    const float* x       = (const float*)d_in[0];
    const float* deltas  = (const float*)d_in[1];
    const float* heights = (const float*)d_in[2];
    float* out = (float*)d_out;

    cudaFuncSetAttribute(tree_kernel, cudaFuncAttributeMaxDynamicSharedMemorySize, DYN_SMEM);
    tree_kernel<<<NCTA, 256, DYN_SMEM>>>(x, deltas, heights, out);
}